// round 17
// baseline (speedup 1.0000x reference)
#include <cuda_runtime.h>

#define BATCH 64
#define CIN   96
#define CHID  256
#define COUT  80
#define TLEN  2048
#define NSM   148

// ---- scratch (allocation-free rule: __device__ globals) ----
static __device__ float    g_z1[(size_t)BATCH * TLEN * CHID];          // [b][t][o]
static __device__ float    g_z2[(size_t)BATCH * TLEN * COUT];          // [b][j][t]
static __device__ unsigned g_xbits[(size_t)BATCH * TLEN * 4];
static __device__ unsigned g_s1bits[(size_t)BATCH * TLEN * (CHID/32)];

// =====================================================================
// K0: build 96-bit input-activity masks per (b,t). Coalesced LDGs.
// =====================================================================
__global__ __launch_bounds__(256) void k0_xbits(const float* __restrict__ x) {
    const int gid = blockIdx.x * 256 + threadIdx.x;   // 0 .. 64*2048-1
    const int b = gid >> 11;
    const int t = gid & 2047;
    const float* xp = x + (size_t)b * CIN * TLEN + t;
    unsigned m0 = 0, m1 = 0, m2 = 0;
    #pragma unroll
    for (int i = 0; i < 32; i++) if (__ldg(xp + (size_t)i * TLEN) != 0.0f)        m0 |= 1u << i;
    #pragma unroll
    for (int i = 0; i < 32; i++) if (__ldg(xp + (size_t)(i + 32) * TLEN) != 0.0f) m1 |= 1u << i;
    #pragma unroll
    for (int i = 0; i < 32; i++) if (__ldg(xp + (size_t)(i + 64) * TLEN) != 0.0f) m2 |= 1u << i;
    *(uint4*)&g_xbits[(size_t)gid * 4] = make_uint4(m0, m1, m2, 0u);
}

// =====================================================================
// K1: layer-1 sparse GEMM, PERSISTENT + o-split. (round-11, unchanged)
// =====================================================================
#define K1_T 128
#define W1ST 528                      // bytes per w1t row (132 floats)
__global__ __launch_bounds__(1024, 2) void k1_gemm1(const float* __restrict__ W1) {
    extern __shared__ char sm[];
    float*          w1t    = (float*)sm;                    // [97][132] = 51216 B
    unsigned short* lists  = (unsigned short*)(sm + 51216); // [128][104] = 26624 B
    int*            counts = (int*)(sm + 77840);            // [128]

    const int tid  = threadIdx.x;
    const int half = (blockIdx.x >= NSM) ? 1 : 0;
    const int slot = blockIdx.x - half * NSM;               // 0..147
    const int o0   = half * 128;

    for (int idx = tid; idx < 128 * CIN; idx += 1024) {
        int ol = idx / CIN, i = idx % CIN;
        w1t[i * 132 + ol] = W1[(size_t)(o0 + ol) * CIN + i];
    }
    for (int idx = tid; idx < 132; idx += 1024) w1t[96 * 132 + idx] = 0.0f;

    const int grp  = tid >> 5;
    const int lane = tid & 31;
    const char* wb = (const char*)w1t + lane * 16;

    const int nwork = (TLEN / K1_T) * BATCH;                // 1024 per half
    for (int w = slot; w < nwork; w += NSM) {
        const int tc = w & 15;
        const int b  = w >> 4;
        const int t0 = tc * K1_T;

        __syncthreads();
        if (tid < K1_T) {
            uint4 mw = *(const uint4*)&g_xbits[((size_t)b * TLEN + t0 + tid) * 4];
            unsigned short* L = lists + tid * 104;
            int c = 0;
            unsigned m = mw.x;
            while (m) { int k = __ffs(m) - 1; m &= m - 1; L[c++] = (unsigned short)(k * W1ST); }
            m = mw.y;
            while (m) { int k = __ffs(m) - 1; m &= m - 1; L[c++] = (unsigned short)((k + 32) * W1ST); }
            m = mw.z;
            while (m) { int k = __ffs(m) - 1; m &= m - 1; L[c++] = (unsigned short)((k + 64) * W1ST); }
            while (c & 3) L[c++] = (unsigned short)(96 * W1ST);
            counts[tid] = c;
        }
        __syncthreads();

        float* zp = g_z1 + ((size_t)b * TLEN + t0) * CHID + o0 + lane * 4;
        for (int tt = grp; tt < K1_T; tt += 32) {
            const unsigned short* L = lists + tt * 104;
            const int cnt = counts[tt];
            float a0 = 0.0f, a1 = 0.0f, a2 = 0.0f, a3 = 0.0f;
            for (int p = 0; p < cnt; p += 4) {
                uint2 e = *(const uint2*)(L + p);
                float4 w0 = *(const float4*)(wb + (e.x & 0xffff));
                float4 w1 = *(const float4*)(wb + (e.x >> 16));
                float4 w2 = *(const float4*)(wb + (e.y & 0xffff));
                float4 w3 = *(const float4*)(wb + (e.y >> 16));
                a0 += w0.x; a1 += w0.y; a2 += w0.z; a3 += w0.w;
                a0 += w1.x; a1 += w1.y; a2 += w1.z; a3 += w1.w;
                a0 += w2.x; a1 += w2.y; a2 += w2.z; a3 += w2.w;
                a0 += w3.x; a1 += w3.y; a2 += w3.z; a3 += w3.w;
            }
            *(float4*)(zp + (size_t)tt * CHID) = make_float4(a0, a1, a2, a3);
        }
    }
}

// =====================================================================
// LIF step: shortened critical chain (set.ge ALU + reset-FMA), bit-exact
// vs reference (sv=1 -> v-v=+0; sv=0 -> v unchanged).
// =====================================================================
__device__ __forceinline__ float lif_step(float& v, float z) {
    v = __fmaf_rn(v, 0.95f, z);
    float sv;
    asm("set.ge.f32.f32 %0, %1, %2;" : "=f"(sv) : "f"(v), "f"(1.0f));
    v = __fmaf_rn(-sv, v, v);
    return sv;
}

// 16-step LIF block WITH ballot-bit accumulation. The s1bits word covers
// 32 steps: keep accumulates across two 16-step blocks; stored when this
// block is the odd phase (tbase & 16).
__device__ __forceinline__ void proc16b(float& v, const float (&z)[16],
                                        int tbase, float* __restrict__ so,
                                        unsigned& keep, unsigned* __restrict__ bw,
                                        int lane) {
    const int stb = tbase & 31;        // 0 or 16: position within the 32-step word
    #pragma unroll
    for (int u8 = 0; u8 < 16; u8 += 8) {
        float sv[8];
        #pragma unroll
        for (int u = 0; u < 8; u++) {
            const int st = stb + u8 + u;
            sv[u] = lif_step(v, z[u8 + u]);
            unsigned bal = __ballot_sync(0xffffffffu, sv[u] != 0.0f);
            keep = (lane == st) ? bal : keep;
        }
        *(float4*)(so + tbase + u8)     = make_float4(sv[0], sv[1], sv[2], sv[3]);
        *(float4*)(so + tbase + u8 + 4) = make_float4(sv[4], sv[5], sv[6], sv[7]);
    }
    if (stb == 16)                      // end of a 32-step word
        bw[(size_t)(tbase - 16 + lane) * (CHID/32)] = keep;
}

__device__ __forceinline__ void proc16(float& v, const float (&z)[16],
                                       int tbase, float* __restrict__ so) {
    #pragma unroll
    for (int u8 = 0; u8 < 16; u8 += 8) {
        float sv[8];
        #pragma unroll
        for (int u = 0; u < 8; u++) sv[u] = lif_step(v, z[u8 + u]);
        *(float4*)(so + tbase + u8)     = make_float4(sv[0], sv[1], sv[2], sv[3]);
        *(float4*)(so + tbase + u8 + 4) = make_float4(sv[4], sv[5], sv[6], sv[7]);
    }
}

// =====================================================================
// K2: layer-1 LIF scan. 128 CTAs x 128 thr = 16384 (one wave).
// 4 rotating 16-step buffers (64 floats of buffer state -> NO register
// spill; the old 4x32 layout needed ~148 regs and spilled to local).
// Prefetch distance 3 = 48 steps (~624 cyc) >= DRAM latency.
// =====================================================================
#define LD16(dst, zp, t) { _Pragma("unroll") \
    for (int u = 0; u < 16; u++) dst[u] = __ldg(zp + (size_t)((t) + u) * CHID); }

__global__ __launch_bounds__(128) void k2_scan1(float* __restrict__ out) {
    const int gid  = blockIdx.x * 128 + threadIdx.x;
    const int b    = gid >> 8;
    const int o    = gid & 255;
    const int lane = o & 31;
    const float* z  = g_z1 + (size_t)b * TLEN * CHID + o;
    float*       so = out + ((size_t)b * CHID + o) * TLEN;
    unsigned*    bw = g_s1bits + (size_t)b * TLEN * (CHID/32) + (o >> 5);

    float A[16], B[16], C[16], D[16];
    float v = 0.0f;
    unsigned keep = 0;
    LD16(A, z, 0); LD16(B, z, 16); LD16(C, z, 32);

    for (int bi = 0; bi < 128; bi += 4) {
        const int t = bi * 16;
        if (bi + 3 < 128) LD16(D, z, t + 48);
        proc16b(v, A, t, so, keep, bw, lane);
        if (bi + 4 < 128) LD16(A, z, t + 64);
        proc16b(v, B, t + 16, so, keep, bw, lane);
        if (bi + 5 < 128) LD16(B, z, t + 80);
        proc16b(v, C, t + 32, so, keep, bw, lane);
        if (bi + 6 < 128) LD16(C, z, t + 96);
        proc16b(v, D, t + 48, so, keep, bw, lane);
    }
}

// =====================================================================
// K3: layer-2 sparse GEMM, PERSISTENT. (round-11, unchanged)
// =====================================================================
#define K3_T 32
__global__ __launch_bounds__(768, 2) void k3_gemm2(const float* __restrict__ W2) {
    extern __shared__ char sm[];
    float*          w2t    = (float*)sm;                    // [80][257] = 82240 B
    unsigned short* lists  = (unsigned short*)(sm + 82240); // [32][264] = 16896 B
    int*            counts = (int*)(sm + 99136);            // [32]
    float*          ztile  = (float*)(sm + 99264);          // [32][81] = 10368 B

    const int tid = threadIdx.x;

    for (int idx = tid; idx < COUT * CHID; idx += 768) {
        int j = idx >> 8, o = idx & 255;
        w2t[j * 257 + o] = W2[idx];
    }
    for (int idx = tid; idx < COUT; idx += 768) w2t[idx * 257 + 256] = 0.0f;

    const int grp = tid / 96;            // 0..7 (3 full warps each)
    const int r   = tid % 96;

    const int nwork = (TLEN / K3_T) * BATCH;                // 4096
    for (int w = blockIdx.x; w < nwork; w += 2 * NSM) {
        const int tc = w & 63;
        const int b  = w >> 6;
        const int t0 = tc * K3_T;

        __syncthreads();
        if (tid < K3_T) {
            const unsigned* sb = g_s1bits + ((size_t)b * TLEN + t0 + tid) * 8;
            unsigned short* L = lists + tid * 264;
            int c = 0;
            #pragma unroll
            for (int ww = 0; ww < 8; ww++) {
                unsigned m = sb[ww];
                while (m) {
                    int k = __ffs(m) - 1;
                    m &= m - 1;
                    L[c++] = (unsigned short)(((ww << 5) + k) << 2);
                }
            }
            while (c & 3) L[c++] = (unsigned short)(256 << 2);
            counts[tid] = c;
        }
        __syncthreads();

        if (r < COUT) {
            const char* wbp = (const char*)(w2t + r * 257);
            for (int q = grp; q < K3_T / 2; q += 8) {
                const int tt = 2 * q;
                const unsigned short* L0 = lists + tt * 264;
                const unsigned short* L1 = L0 + 264;
                const int c0 = counts[tt], c1 = counts[tt + 1];
                const int cmin = c0 < c1 ? c0 : c1;
                float a0 = 0.0f, a1 = 0.0f;
                int p = 0;
                for (; p < cmin; p += 4) {   // two interleaved chains
                    uint2 e0 = *(const uint2*)(L0 + p);
                    uint2 e1 = *(const uint2*)(L1 + p);
                    a0 += *(const float*)(wbp + (e0.x & 0xffff));
                    a1 += *(const float*)(wbp + (e1.x & 0xffff));
                    a0 += *(const float*)(wbp + (e0.x >> 16));
                    a1 += *(const float*)(wbp + (e1.x >> 16));
                    a0 += *(const float*)(wbp + (e0.y & 0xffff));
                    a1 += *(const float*)(wbp + (e1.y & 0xffff));
                    a0 += *(const float*)(wbp + (e0.y >> 16));
                    a1 += *(const float*)(wbp + (e1.y >> 16));
                }
                for (; p < c0; p += 4) {
                    uint2 e0 = *(const uint2*)(L0 + p);
                    a0 += *(const float*)(wbp + (e0.x & 0xffff));
                    a0 += *(const float*)(wbp + (e0.x >> 16));
                    a0 += *(const float*)(wbp + (e0.y & 0xffff));
                    a0 += *(const float*)(wbp + (e0.y >> 16));
                }
                for (; p < c1; p += 4) {
                    uint2 e1 = *(const uint2*)(L1 + p);
                    a1 += *(const float*)(wbp + (e1.x & 0xffff));
                    a1 += *(const float*)(wbp + (e1.x >> 16));
                    a1 += *(const float*)(wbp + (e1.y & 0xffff));
                    a1 += *(const float*)(wbp + (e1.y >> 16));
                }
                ztile[tt * 81 + r]       = a0;
                ztile[(tt + 1) * 81 + r] = a1;
            }
        }
        __syncthreads();

        float* zo = g_z2 + (size_t)b * COUT * TLEN + t0;
        for (int idx = tid; idx < COUT * (K3_T / 4); idx += 768) {
            int j = idx >> 3, q = idx & 7;
            float4 vv = make_float4(ztile[(4 * q + 0) * 81 + j],
                                    ztile[(4 * q + 1) * 81 + j],
                                    ztile[(4 * q + 2) * 81 + j],
                                    ztile[(4 * q + 3) * 81 + j]);
            *(float4*)(zo + (size_t)j * TLEN + 4 * q) = vv;
        }
    }
}

// =====================================================================
// K4: layer-2 LIF scan. 160 CTAs x 32 thr, 4 rotating 16-step buffers
// (no spill), contiguous float4 loads. (round-16, unchanged)
// =====================================================================
#define LD16C(dst, zp, t) { _Pragma("unroll") \
    for (int u = 0; u < 4; u++) *(float4*)((dst) + 4 * u) = \
        __ldg((const float4*)((zp) + (t)) + u); }

__global__ __launch_bounds__(32) void k4_scan2(float* __restrict__ out) {
    const int gid = blockIdx.x * 32 + threadIdx.x;   // 0..5119
    const int b = gid / COUT;
    const int j = gid % COUT;
    const float* z  = g_z2 + ((size_t)b * COUT + j) * TLEN;
    float*       so = out + (size_t)BATCH * CHID * TLEN
                          + ((size_t)b * COUT + j) * TLEN;

    float A[16], B[16], C[16], D[16];
    float v = 0.0f;
    LD16C(A, z, 0); LD16C(B, z, 16); LD16C(C, z, 32);

    for (int bi = 0; bi < 128; bi += 4) {
        const int t = bi * 16;
        if (bi + 3 < 128) LD16C(D, z, t + 48);
        proc16(v, A, t, so);
        if (bi + 4 < 128) LD16C(A, z, t + 64);
        proc16(v, B, t + 16, so);
        if (bi + 5 < 128) LD16C(B, z, t + 80);
        proc16(v, C, t + 32, so);
        if (bi + 6 < 128) LD16C(C, z, t + 96);
        proc16(v, D, t + 48, so);
    }
}

// =====================================================================
extern "C" void kernel_launch(void* const* d_in, const int* in_sizes, int n_in,
                              void* d_out, int out_size) {
    const float* x  = (const float*)d_in[0];   // [64, 96, 2048]
    const float* W1 = (const float*)d_in[1];   // [256, 96]
    const float* W2 = (const float*)d_in[2];   // [80, 256]
    float* out = (float*)d_out;                // spk1 ++ spk2

    const int smem1 = 77840 + 512;             // 78352  -> 2 CTAs/SM
    const int smem3 = 99264 + 10368;           // 109632 -> 2 CTAs/SM
    cudaFuncSetAttribute(k1_gemm1, cudaFuncAttributeMaxDynamicSharedMemorySize, smem1);
    cudaFuncSetAttribute(k3_gemm2, cudaFuncAttributeMaxDynamicSharedMemorySize, smem3);

    k0_xbits<<<(BATCH * TLEN) / 256, 256>>>(x);
    k1_gemm1<<<2 * NSM, 1024, smem1>>>(W1);
    k2_scan1<<<(BATCH * CHID) / 128, 128>>>(out);
    k3_gemm2<<<2 * NSM, 768, smem3>>>(W2);
    k4_scan2<<<(BATCH * COUT) / 32, 32>>>(out);
}